// round 1
// baseline (speedup 1.0000x reference)
#include <cuda_runtime.h>

// Problem constants (fixed by setup_inputs)
#define MP_C 10242            // pooled vertices (output rows per batch)
#define M_C 40962             // input vertices
#define F_C 128               // features
#define B_C 16                // batch
#define NNZ_MAX 65536         // >= 40968

// Scratch state, rebuilt every launch (graph-replay safe, no allocations)
__device__ int g_rows[NNZ_MAX];
__device__ int g_cols[NNZ_MAX];
__device__ int g_counts[MP_C];
__device__ int g_cursor[MP_C];
__device__ int g_starts[MP_C + 1];
__device__ int g_csr[NNZ_MAX];
__device__ int g_is64;

// --- K0: detect whether rows/cols are int64 or int32 -----------------------
// If data is int64 (values < 2^31, nonnegative), every odd 32-bit word is 0.
// If int32, the odd words are random row indices; P(all 64 zero) ~ 10242^-64.
__global__ void k_detect(const unsigned int* __restrict__ rows_raw) {
    int any = 0;
    for (int i = 0; i < 64; ++i) {
        if (rows_raw[2 * i + 1] != 0u) { any = 1; break; }
    }
    g_is64 = any ? 0 : 1;
}

// --- K1: normalize indices to int32 ----------------------------------------
__global__ void k_decode(const void* __restrict__ rows,
                         const void* __restrict__ cols, int nnz) {
    int i = blockIdx.x * blockDim.x + threadIdx.x;
    if (i >= nnz) return;
    if (g_is64) {
        g_rows[i] = (int)((const long long*)rows)[i];
        g_cols[i] = (int)((const long long*)cols)[i];
    } else {
        g_rows[i] = ((const int*)rows)[i];
        g_cols[i] = ((const int*)cols)[i];
    }
}

// --- K2: zero per-row counters ---------------------------------------------
__global__ void k_zero() {
    int i = blockIdx.x * blockDim.x + threadIdx.x;
    if (i < MP_C) { g_counts[i] = 0; g_cursor[i] = 0; }
}

// --- K3: histogram rows -----------------------------------------------------
__global__ void k_count(int nnz) {
    int i = blockIdx.x * blockDim.x + threadIdx.x;
    if (i < nnz) atomicAdd(&g_counts[g_rows[i]], 1);
}

// --- K4: exclusive prefix sum over counts -> starts (single block) ---------
__global__ void k_scan() {
    __shared__ int sh[1024];
    __shared__ int carry_s;
    int tid = threadIdx.x;
    if (tid == 0) carry_s = 0;
    __syncthreads();
    for (int base = 0; base < MP_C; base += 1024) {
        int i = base + tid;
        int v = (i < MP_C) ? g_counts[i] : 0;
        sh[tid] = v;
        __syncthreads();
        for (int off = 1; off < 1024; off <<= 1) {
            int t = (tid >= off) ? sh[tid - off] : 0;
            __syncthreads();
            sh[tid] += t;
            __syncthreads();
        }
        int incl = sh[tid];
        int carry = carry_s;
        if (i < MP_C) g_starts[i] = carry + incl - v;  // exclusive
        __syncthreads();
        if (tid == 0) carry_s = carry + sh[1023];
        __syncthreads();
    }
    if (tid == 0) g_starts[MP_C] = carry_s;
}

// --- K5: scatter nnz ids into CSR slots (order fixed up by K6) -------------
__global__ void k_scatter(int nnz) {
    int i = blockIdx.x * blockDim.x + threadIdx.x;
    if (i < nnz) {
        int r = g_rows[i];
        int pos = atomicAdd(&g_cursor[r], 1);
        g_csr[g_starts[r] + pos] = i;
    }
}

// --- K6: per-row insertion sort (rows are ~4 long) => deterministic sums ---
__global__ void k_sort() {
    int p = blockIdx.x * blockDim.x + threadIdx.x;
    if (p >= MP_C) return;
    int s = g_starts[p], e = g_starts[p + 1];
    for (int i = s + 1; i < e; ++i) {
        int key = g_csr[i];
        int j = i - 1;
        while (j >= s && g_csr[j] > key) { g_csr[j + 1] = g_csr[j]; --j; }
        g_csr[j + 1] = key;
    }
}

// --- K7: main pooled gather. One warp per (b, p) output row. ---------------
// Lane l handles float4 at feature offset 4l (512B contiguous per row).
__global__ void __launch_bounds__(256) k_pool(
    const float* __restrict__ x,
    const float* __restrict__ vals,
    float* __restrict__ out
) {
    int w = (int)((blockIdx.x * 256u + threadIdx.x) >> 5);
    int lane = threadIdx.x & 31;
    if (w >= B_C * MP_C) return;
    int b = w / MP_C;
    int p = w - b * MP_C;
    int s = g_starts[p];
    int e = g_starts[p + 1];
    const float4* __restrict__ xb =
        (const float4*)(x + (size_t)b * M_C * F_C);
    float4 acc = make_float4(0.f, 0.f, 0.f, 0.f);
    for (int i = s; i < e; ++i) {
        int k = g_csr[i];
        int c = g_cols[k];
        float v = __ldg(&vals[k]);
        float4 d = xb[(size_t)c * (F_C / 4) + lane];
        acc.x = fmaf(v, d.x, acc.x);
        acc.y = fmaf(v, d.y, acc.y);
        acc.z = fmaf(v, d.z, acc.z);
        acc.w = fmaf(v, d.w, acc.w);
    }
    // out index: w = b*MP + p matches [B, Mp, F] layout exactly
    ((float4*)out)[(size_t)w * (F_C / 4) + lane] = acc;
}

extern "C" void kernel_launch(void* const* d_in, const int* in_sizes, int n_in,
                              void* d_out, int out_size) {
    const float* x    = (const float*)d_in[0];
    const void*  rows = d_in[1];
    const void*  cols = d_in[2];
    const float* vals = (const float*)d_in[3];
    float* out = (float*)d_out;
    int nnz = in_sizes[1];
    if (nnz > NNZ_MAX) nnz = NNZ_MAX;

    int tb = 256;
    k_detect<<<1, 1>>>((const unsigned int*)rows);
    k_decode<<<(nnz + tb - 1) / tb, tb>>>(rows, cols, nnz);
    k_zero<<<(MP_C + tb - 1) / tb, tb>>>();
    k_count<<<(nnz + tb - 1) / tb, tb>>>(nnz);
    k_scan<<<1, 1024>>>();
    k_scatter<<<(nnz + tb - 1) / tb, tb>>>(nnz);
    k_sort<<<(MP_C + tb - 1) / tb, tb>>>();

    int total_threads = B_C * MP_C * 32;              // one warp per (b,p)
    k_pool<<<(total_threads + tb - 1) / tb, tb>>>(x, vals, out);
}

// round 2
// speedup vs baseline: 1.2424x; 1.2424x over previous
#include <cuda_runtime.h>

// Problem constants (fixed by setup_inputs)
#define MP_C 10242            // pooled vertices (output rows per batch)
#define M_C 40962             // input vertices
#define F_C 128               // features
#define B_C 16                // batch
#define NNZ_MAX 65536
#define SLOT_DEPTH 64         // max entries per pooled row (Poisson(4); P(>64)~0)
#define BB 8                  // batches per pool-warp
#define NGRP (B_C / BB)       // batch groups

// Scratch (device globals: no allocation allowed)
__device__ int   g_counts[MP_C];
__device__ int   g_slotk[MP_C * SLOT_DEPTH];   // nnz id (sort key, distinct)
__device__ int   g_slotc[MP_C * SLOT_DEPTH];   // column
__device__ float g_slotv[MP_C * SLOT_DEPTH];   // value
__device__ int   g_is64;

// --- K0: zero counters + detect int64 vs int32 indices ---------------------
// int64 little-endian: high 32-bit words are 0 (indices < 2^15). For int32
// data the odd words are random row indices; P(64 zeros) ~ 10242^-64.
__global__ void k_prep(const unsigned int* __restrict__ rows_raw) {
    int i = blockIdx.x * blockDim.x + threadIdx.x;
    if (i < MP_C) g_counts[i] = 0;
    if (i == 0) {
        unsigned int acc = 0;
        #pragma unroll
        for (int j = 0; j < 64; ++j) acc |= rows_raw[2 * j + 1];
        g_is64 = (acc == 0u) ? 1 : 0;
    }
}

// --- K1: decode indices + scatter (id, col, val) into per-row slots --------
__global__ void k_scatter(const void* __restrict__ rows,
                          const void* __restrict__ cols,
                          const float* __restrict__ vals, int nnz) {
    int i = blockIdx.x * blockDim.x + threadIdx.x;
    if (i >= nnz) return;
    int r, c;
    if (g_is64) {
        r = (int)((const long long*)rows)[i];
        c = (int)((const long long*)cols)[i];
    } else {
        r = ((const int*)rows)[i];
        c = ((const int*)cols)[i];
    }
    int pos = atomicAdd(&g_counts[r], 1);
    if (pos < SLOT_DEPTH) {
        int idx = r * SLOT_DEPTH + pos;
        g_slotk[idx] = i;
        g_slotc[idx] = c;
        g_slotv[idx] = vals[i];
    }
}

// --- K2: pooled gather. One warp per (p, batch-group of BB). ---------------
// Lane l owns float4 feature chunk [4l, 4l+4). Slot entries are loaded in
// parallel by lanes, rank-sorted by nnz id for a deterministic summation
// order, then each sorted step gathers BB independent 512B x rows.
__global__ void __launch_bounds__(256) k_pool(
    const float4* __restrict__ x4,
    float4* __restrict__ out4
) {
    int w = (int)(blockIdx.x * 8u + (threadIdx.x >> 5));
    int lane = threadIdx.x & 31;
    if (w >= MP_C * NGRP) return;
    int p   = w >> 1;          // adjacent warps share p (index loads hit L1)
    int grp = w & (NGRP - 1);
    int b0  = grp * BB;

    int cnt = g_counts[p];
    if (cnt > SLOT_DEPTH) cnt = SLOT_DEPTH;
    int base = p * SLOT_DEPTH;

    float4 acc[BB];
    #pragma unroll
    for (int bb = 0; bb < BB; ++bb) acc[bb] = make_float4(0.f, 0.f, 0.f, 0.f);

    const unsigned FULL = 0xFFFFFFFFu;

    if (cnt <= 32) {
        // Hot path: lanes 0..cnt-1 hold one entry each (parallel loads).
        int   key = 0x7FFFFFFF;
        int   c   = 0;
        float v   = 0.f;
        if (lane < cnt) {
            key = g_slotk[base + lane];
            c   = g_slotc[base + lane];
            v   = g_slotv[base + lane];
        }
        // Rank by key (keys are distinct nnz ids) -> deterministic order.
        int rank = 0;
        for (int j = 0; j < cnt; ++j) {
            int kj = __shfl_sync(FULL, key, j);
            if (lane < cnt && kj < key) rank++;
        }
        for (int t = 0; t < cnt; ++t) {
            unsigned m = __ballot_sync(FULL, rank == t && lane < cnt);
            int src = __ffs(m) - 1;
            int   ct = __shfl_sync(FULL, c, src);
            float vt = __shfl_sync(FULL, v, src);
            size_t off = ((size_t)b0 * M_C + (size_t)ct) * (F_C / 4) + lane;
            #pragma unroll
            for (int bb = 0; bb < BB; ++bb) {
                float4 d = x4[off + (size_t)bb * ((size_t)M_C * (F_C / 4))];
                acc[bb].x = fmaf(vt, d.x, acc[bb].x);
                acc[bb].y = fmaf(vt, d.y, acc[bb].y);
                acc[bb].z = fmaf(vt, d.z, acc[bb].z);
                acc[bb].w = fmaf(vt, d.w, acc[bb].w);
            }
        }
    } else {
        // Rare path (32 < cnt <= 64): deterministic selection by ascending id.
        int last = -1;
        for (int t = 0; t < cnt; ++t) {
            int best = 0x7FFFFFFF, bi = -1;
            for (int j = lane; j < cnt; j += 32) {
                int k2 = g_slotk[base + j];
                if (k2 > last && k2 < best) { best = k2; bi = j; }
            }
            #pragma unroll
            for (int o = 16; o; o >>= 1) {
                int ob  = __shfl_xor_sync(FULL, best, o);
                int obi = __shfl_xor_sync(FULL, bi, o);
                if (ob < best) { best = ob; bi = obi; }
            }
            last = best;
            int   ct = g_slotc[base + bi];
            float vt = g_slotv[base + bi];
            size_t off = ((size_t)b0 * M_C + (size_t)ct) * (F_C / 4) + lane;
            #pragma unroll
            for (int bb = 0; bb < BB; ++bb) {
                float4 d = x4[off + (size_t)bb * ((size_t)M_C * (F_C / 4))];
                acc[bb].x = fmaf(vt, d.x, acc[bb].x);
                acc[bb].y = fmaf(vt, d.y, acc[bb].y);
                acc[bb].z = fmaf(vt, d.z, acc[bb].z);
                acc[bb].w = fmaf(vt, d.w, acc[bb].w);
            }
        }
    }

    // out layout [B, Mp, F]: float4 index ((b*MP + p)*32 + lane)
    #pragma unroll
    for (int bb = 0; bb < BB; ++bb) {
        out4[((size_t)(b0 + bb) * MP_C + (size_t)p) * (F_C / 4) + lane] = acc[bb];
    }
}

extern "C" void kernel_launch(void* const* d_in, const int* in_sizes, int n_in,
                              void* d_out, int out_size) {
    const float* x    = (const float*)d_in[0];
    const void*  rows = d_in[1];
    const void*  cols = d_in[2];
    const float* vals = (const float*)d_in[3];
    float* out = (float*)d_out;
    int nnz = in_sizes[1];
    if (nnz > NNZ_MAX) nnz = NNZ_MAX;

    const int tb = 256;
    k_prep<<<(MP_C + tb - 1) / tb, tb>>>((const unsigned int*)rows);
    k_scatter<<<(nnz + tb - 1) / tb, tb>>>(rows, cols, vals, nnz);

    int warps = MP_C * NGRP;
    int blocks = (warps + 7) / 8;
    k_pool<<<blocks, tb>>>((const float4*)x, (float4*)out);
}